// round 4
// baseline (speedup 1.0000x reference)
#include <cuda_runtime.h>
#include <cuda_bf16.h>
#include <math.h>

// Per-chunk partial score sums (B * CPB = 64*128 = 8192 here; headroom).
__device__ float g_partial[1 << 15];

__device__ __forceinline__ unsigned f2ord(float x) {
    unsigned b = __float_as_uint(x);
    return (b & 0x80000000u) ? ~b : (b | 0x80000000u);
}
__device__ __forceinline__ float ord2f(unsigned u) {
    return __uint_as_float((u & 0x80000000u) ? (u ^ 0x80000000u) : ~u);
}

// Warp argmax (first index) of a 128-wide row. Returns index; Mu_out = ordered max.
__device__ __forceinline__ int warp_argmax128(float4 v, int lane, unsigned* Mu_out) {
    float m = v.x; int mi = 0;
    if (v.y > m) { m = v.y; mi = 1; }
    if (v.z > m) { m = v.z; mi = 2; }
    if (v.w > m) { m = v.w; mi = 3; }
    mi += lane * 4;
    unsigned mu = f2ord(m);
    unsigned Mu = __reduce_max_sync(0xFFFFFFFFu, mu);
    unsigned cand = (mu == Mu) ? (unsigned)mi : 0xFFFFFFFFu;
    *Mu_out = Mu;
    return (int)__reduce_min_sync(0xFFFFFFFFu, cand);
}

// ---------------------------------------------------------------------------
// Fused kernel (V=128, T % (4*CPB_div) rows): each warp owns C=T/CPB
// consecutive frames of one batch row. Computes token, keep, and a masked
// partial score sum. prev-token at chunk start is recomputed (1 extra row).
// ---------------------------------------------------------------------------
__global__ void ctc_fused_v128(const float* __restrict__ feat,
                               const int* __restrict__ lengths,
                               float* __restrict__ tok_out,
                               float* __restrict__ keep_out,
                               int T, int CPB) {
    const int lane  = threadIdx.x & 31;
    const int chunk = (blockIdx.x * blockDim.x + threadIdx.x) >> 5;
    const int C   = T / CPB;
    const int b   = chunk / CPB;
    const int c   = chunk - b * CPB;
    const int t0  = c * C;
    const int len = lengths[b];
    const size_t row0 = (size_t)b * T + t0;
    const float4* f4 = reinterpret_cast<const float4*>(feat);

    // prev token entering this chunk
    int prev = 0;
    if (c != 0) {
        unsigned Mu;
        prev = warp_argmax128(f4[(row0 - 1) * 32 + lane], lane, &Mu);
    }

    float acc = 0.f;
    for (int g = 0; g < C; g += 4) {
        float4 v[4];
        #pragma unroll
        for (int r = 0; r < 4; r++)
            v[r] = f4[(row0 + g + r) * 32 + lane];

        int   tokv[4];
        float sc[4];
        #pragma unroll
        for (int r = 0; r < 4; r++) {
            unsigned Mu;
            tokv[r] = warp_argmax128(v[r], lane, &Mu);
            int t = t0 + g + r;
            if (t < len) {                      // warp-uniform branch
                float M = ord2f(Mu);
                float s = __expf(v[r].x - M) + __expf(v[r].y - M) +
                          __expf(v[r].z - M) + __expf(v[r].w - M);
                #pragma unroll
                for (int o = 16; o; o >>= 1)
                    s += __shfl_xor_sync(0xFFFFFFFFu, s, o);
                sc[r] = -__logf(s);             // max(log_softmax) = -log(Σexp(x-M))
            } else {
                sc[r] = 0.f;
            }
        }

        if (lane == 0) {
            float4 tf, kf;
            float* tfp = &tf.x; float* kfp = &kf.x;
            #pragma unroll
            for (int r = 0; r < 4; r++) {
                int cur = tokv[r];
                int t = t0 + g + r;
                tfp[r] = (float)cur;
                kfp[r] = (cur != 0 && cur != prev && t < len) ? 1.f : 0.f;
                prev = cur;
                acc += sc[r];
            }
            *reinterpret_cast<float4*>(tok_out  + row0 + g) = tf;
            *reinterpret_cast<float4*>(keep_out + row0 + g) = kf;
        }
    }

    if (lane == 0) g_partial[chunk] = acc;
}

// Deterministic per-batch reduction of CPB chunk partials. One warp per batch.
__global__ void ctc_score_reduce(float* __restrict__ score_out, int CPB) {
    int b = blockIdx.x;
    float s = 0.f;
    for (int i = threadIdx.x; i < CPB; i += 32) s += g_partial[b * CPB + i];
    #pragma unroll
    for (int o = 16; o; o >>= 1) s += __shfl_xor_sync(0xFFFFFFFFu, s, o);
    if (threadIdx.x == 0) score_out[b] = s;
}

// ---------------------------------------------------------------------------
// Generic fallbacks (any V / T). Not expected to run for this shape.
// ---------------------------------------------------------------------------
__device__ float g_maxscore[1 << 19];

__global__ void ctc_pass1_gen(const float* __restrict__ feat,
                              float* __restrict__ tok_out,
                              int rows, int V) {
    int warp = (blockIdx.x * blockDim.x + threadIdx.x) >> 5;
    int lane = threadIdx.x & 31;
    if (warp >= rows) return;
    const float* row = feat + (size_t)warp * V;

    float m = -INFINITY; int mi = 0;
    for (int i = lane; i < V; i += 32) {
        float x = row[i];
        if (x > m) { m = x; mi = i; }
    }
    #pragma unroll
    for (int o = 16; o; o >>= 1) {
        float om = __shfl_xor_sync(0xFFFFFFFFu, m, o);
        int   oi = __shfl_xor_sync(0xFFFFFFFFu, mi, o);
        if (om > m || (om == m && oi < mi)) { m = om; mi = oi; }
    }
    float s = 0.f;
    for (int i = lane; i < V; i += 32) s += __expf(row[i] - m);
    #pragma unroll
    for (int o = 16; o; o >>= 1) s += __shfl_xor_sync(0xFFFFFFFFu, s, o);
    if (lane == 0) { tok_out[warp] = (float)mi; g_maxscore[warp] = -__logf(s); }
}

__global__ void ctc_pass2_gen(const float* __restrict__ tok,
                              const int* __restrict__ lengths,
                              float* __restrict__ keep_out,
                              float* __restrict__ score_out,
                              int T) {
    int b = blockIdx.x;
    int len = lengths[b];
    const float* trow = tok + (size_t)b * T;
    float* krow = keep_out + (size_t)b * T;
    const float* srow = g_maxscore + (size_t)b * T;

    float acc = 0.f;
    for (int t = threadIdx.x; t < T; t += blockDim.x) {
        int cur  = (int)trow[t];
        int prev = (t == 0) ? 0 : (int)trow[t - 1];
        bool valid = (t < len);
        krow[t] = (cur != 0 && cur != prev && valid) ? 1.f : 0.f;
        if (valid) acc += srow[t];
    }
    #pragma unroll
    for (int o = 16; o; o >>= 1) acc += __shfl_xor_sync(0xFFFFFFFFu, acc, o);
    __shared__ float sh[32];
    int wid = threadIdx.x >> 5;
    if ((threadIdx.x & 31) == 0) sh[wid] = acc;
    __syncthreads();
    if (threadIdx.x == 0) {
        float s = 0.f;
        int nw = blockDim.x >> 5;
        for (int w = 0; w < nw; w++) s += sh[w];
        score_out[b] = s;
    }
}

extern "C" void kernel_launch(void* const* d_in, const int* in_sizes, int n_in,
                              void* d_out, int out_size) {
    const float* feat    = (const float*)d_in[0];
    const int*   lengths = (const int*)d_in[1];

    int B = in_sizes[1];
    int T = (out_size - B) / (2 * B);          // out = tokens(B*T) + keep(B*T) + scores(B)
    int V = (int)((long long)in_sizes[0] / ((long long)B * T));
    int rows = B * T;

    float* out   = (float*)d_out;
    float* tok   = out;
    float* keep  = out + (size_t)rows;
    float* score = out + 2 * (size_t)rows;

    const int CPB = 128;                       // chunks per batch row
    if (V == 128 && T % (CPB * 4) == 0 && B * CPB <= (1 << 15)) {
        int warps  = B * CPB;                  // 8192 for this shape
        int blocks = warps / 8;                // 256-thread blocks
        ctc_fused_v128<<<blocks, 256>>>(feat, lengths, tok, keep, T, CPB);
        ctc_score_reduce<<<B, 32>>>(score, CPB);
    } else {
        ctc_pass1_gen<<<(rows + 7) / 8, 256>>>(feat, tok, rows, V);
        ctc_pass2_gen<<<B, 256>>>(tok, lengths, keep, score, T);
    }
}

// round 5
// speedup vs baseline: 1.1689x; 1.1689x over previous
#include <cuda_runtime.h>
#include <cuda_bf16.h>
#include <math.h>

// Scratch for generic fallback path only.
__device__ float g_maxscore[1 << 19];

__device__ __forceinline__ unsigned f2ord(float x) {
    unsigned b = __float_as_uint(x);
    return (b & 0x80000000u) ? ~b : (b | 0x80000000u);
}
__device__ __forceinline__ float ord2f(unsigned u) {
    return __uint_as_float((u & 0x80000000u) ? (u ^ 0x80000000u) : ~u);
}

// ---------------------------------------------------------------------------
// Pass 1 (V=128, T%8==0): one warp per group of 8 consecutive rows (same b).
// 8 front-batched LDG.128, REDUX max/argmax per row, exp-sum only for t<len,
// warp partial score atomicAdd'ed into score_out[b] (zeroed by memset node).
// ---------------------------------------------------------------------------
__global__ void __launch_bounds__(256) ctc_pass1_v128x8(
    const float* __restrict__ feat, const int* __restrict__ lengths,
    float* __restrict__ tok_out, float* __restrict__ score_out, int T)
{
    const int lane = threadIdx.x & 31;
    const int grp  = (blockIdx.x * blockDim.x + threadIdx.x) >> 5;
    const int row0 = grp * 8;
    const int b    = row0 / T;            // T % 8 == 0 -> group within one batch
    const int t0   = row0 - b * T;
    const int len  = lengths[b];
    const float4* f4 = reinterpret_cast<const float4*>(feat);

    float4 v[8];
    #pragma unroll
    for (int r = 0; r < 8; r++)
        v[r] = f4[(size_t)(row0 + r) * 32 + lane];

    float tokv[8];
    unsigned Mus[8];
    #pragma unroll
    for (int r = 0; r < 8; r++) {
        float m = v[r].x; int mi = 0;
        if (v[r].y > m) { m = v[r].y; mi = 1; }
        if (v[r].z > m) { m = v[r].z; mi = 2; }
        if (v[r].w > m) { m = v[r].w; mi = 3; }
        mi += lane * 4;
        unsigned mu = f2ord(m);
        unsigned Mu = __reduce_max_sync(0xFFFFFFFFu, mu);
        unsigned cand = (mu == Mu) ? (unsigned)mi : 0xFFFFFFFFu;
        tokv[r] = (float)__reduce_min_sync(0xFFFFFFFFu, cand);
        Mus[r] = Mu;
    }

    // masked score: only rows with t < len need the log-sum-exp
    float acc = 0.f;
    const int nvalid = len - t0;              // rows [0, nvalid) of this group valid
    #pragma unroll
    for (int r = 0; r < 8; r++) {
        if (r < nvalid) {                     // warp-uniform
            float M = ord2f(Mus[r]);
            float s = __expf(v[r].x - M) + __expf(v[r].y - M) +
                      __expf(v[r].z - M) + __expf(v[r].w - M);
            #pragma unroll
            for (int o = 16; o; o >>= 1)
                s += __shfl_xor_sync(0xFFFFFFFFu, s, o);
            acc += -__logf(s);                // max(log_softmax) = -log(Σexp(x-M))
        }
    }

    if (lane == 0) {
        *reinterpret_cast<float4*>(tok_out + row0) =
            make_float4(tokv[0], tokv[1], tokv[2], tokv[3]);
        *reinterpret_cast<float4*>(tok_out + row0 + 4) =
            make_float4(tokv[4], tokv[5], tokv[6], tokv[7]);
        if (nvalid > 0) atomicAdd(score_out + b, acc);
    }
}

// ---------------------------------------------------------------------------
// Pass 2: keep mask only. Grid = B*S blocks; each handles T/S frames (L2-hot).
// keep = (tok != 0) && (tok != prev) && (t < len)
// ---------------------------------------------------------------------------
__global__ void ctc_pass2_keep(const float* __restrict__ tok,
                               const int* __restrict__ lengths,
                               float* __restrict__ keep_out,
                               int T, int S)
{
    const int b = blockIdx.x / S;
    const int s = blockIdx.x - b * S;
    const int len = lengths[b];
    const int chunk = T / S;                  // multiple of 4
    const size_t base = (size_t)b * T + (size_t)s * chunk;
    const float4* t4 = reinterpret_cast<const float4*>(tok + base);
    float4* k4       = reinterpret_cast<float4*>(keep_out + base);
    const int n4 = chunk >> 2;

    for (int i = threadIdx.x; i < n4; i += blockDim.x) {
        float4 tv = t4[i];
        int gt = s * chunk + 4 * i;           // global t of tv.x
        int p  = (gt == 0) ? 0 : (int)tok[base + 4 * i - 1];
        int c0 = (int)tv.x, c1 = (int)tv.y, c2 = (int)tv.z, c3 = (int)tv.w;
        float4 kv;
        kv.x = (c0 != 0 && c0 != p  && gt     < len) ? 1.f : 0.f;
        kv.y = (c1 != 0 && c1 != c0 && gt + 1 < len) ? 1.f : 0.f;
        kv.z = (c2 != 0 && c2 != c1 && gt + 2 < len) ? 1.f : 0.f;
        kv.w = (c3 != 0 && c3 != c2 && gt + 3 < len) ? 1.f : 0.f;
        k4[i] = kv;
    }
}

// ---------------------------------------------------------------------------
// Generic fallbacks (any V / T). Not expected to run for this shape.
// ---------------------------------------------------------------------------
__global__ void ctc_pass1_gen(const float* __restrict__ feat,
                              float* __restrict__ tok_out,
                              int rows, int V) {
    int warp = (blockIdx.x * blockDim.x + threadIdx.x) >> 5;
    int lane = threadIdx.x & 31;
    if (warp >= rows) return;
    const float* row = feat + (size_t)warp * V;

    float m = -INFINITY; int mi = 0;
    for (int i = lane; i < V; i += 32) {
        float x = row[i];
        if (x > m) { m = x; mi = i; }
    }
    #pragma unroll
    for (int o = 16; o; o >>= 1) {
        float om = __shfl_xor_sync(0xFFFFFFFFu, m, o);
        int   oi = __shfl_xor_sync(0xFFFFFFFFu, mi, o);
        if (om > m || (om == m && oi < mi)) { m = om; mi = oi; }
    }
    float s = 0.f;
    for (int i = lane; i < V; i += 32) s += __expf(row[i] - m);
    #pragma unroll
    for (int o = 16; o; o >>= 1) s += __shfl_xor_sync(0xFFFFFFFFu, s, o);
    if (lane == 0) { tok_out[warp] = (float)mi; g_maxscore[warp] = -__logf(s); }
}

__global__ void ctc_pass2_gen(const float* __restrict__ tok,
                              const int* __restrict__ lengths,
                              float* __restrict__ keep_out,
                              float* __restrict__ score_out,
                              int T) {
    int b = blockIdx.x;
    int len = lengths[b];
    const float* trow = tok + (size_t)b * T;
    float* krow = keep_out + (size_t)b * T;
    const float* srow = g_maxscore + (size_t)b * T;

    float acc = 0.f;
    for (int t = threadIdx.x; t < T; t += blockDim.x) {
        int cur  = (int)trow[t];
        int prev = (t == 0) ? 0 : (int)trow[t - 1];
        bool valid = (t < len);
        krow[t] = (cur != 0 && cur != prev && valid) ? 1.f : 0.f;
        if (valid) acc += srow[t];
    }
    #pragma unroll
    for (int o = 16; o; o >>= 1) acc += __shfl_xor_sync(0xFFFFFFFFu, acc, o);
    __shared__ float sh[32];
    int wid = threadIdx.x >> 5;
    if ((threadIdx.x & 31) == 0) sh[wid] = acc;
    __syncthreads();
    if (threadIdx.x == 0) {
        float s = 0.f;
        int nw = blockDim.x >> 5;
        for (int w = 0; w < nw; w++) s += sh[w];
        score_out[b] = s;
    }
}

extern "C" void kernel_launch(void* const* d_in, const int* in_sizes, int n_in,
                              void* d_out, int out_size) {
    const float* feat    = (const float*)d_in[0];
    const int*   lengths = (const int*)d_in[1];

    int B = in_sizes[1];
    int T = (out_size - B) / (2 * B);          // out = tokens(B*T) + keep(B*T) + scores(B)
    int V = (int)((long long)in_sizes[0] / ((long long)B * T));
    int rows = B * T;

    float* out   = (float*)d_out;
    float* tok   = out;
    float* keep  = out + (size_t)rows;
    float* score = out + 2 * (size_t)rows;

    const int S = 8;                           // pass2 splits per batch row
    if (V == 128 && (T % 8) == 0 && (T % (4 * S)) == 0) {
        cudaMemsetAsync(score, 0, (size_t)B * sizeof(float), 0);
        int groups = rows / 8;                 // one warp per group
        int blocks = (groups + 7) / 8;         // 8 warps / 256-thread block
        ctc_pass1_v128x8<<<blocks, 256>>>(feat, lengths, tok, score, T);
        ctc_pass2_keep<<<B * S, 128>>>(tok, lengths, keep, T, S);
    } else {
        ctc_pass1_gen<<<(rows + 7) / 8, 256>>>(feat, tok, rows, V);
        ctc_pass2_gen<<<B, 256>>>(tok, lengths, keep, score, T);
    }
}

// round 7
// speedup vs baseline: 1.1982x; 1.0250x over previous
#include <cuda_runtime.h>
#include <cuda_bf16.h>
#include <math.h>

// Scratch for generic fallback path only.
__device__ float g_maxscore[1 << 19];

__device__ __forceinline__ unsigned f2ord(float x) {
    unsigned b = __float_as_uint(x);
    return (b & 0x80000000u) ? ~b : (b | 0x80000000u);
}
__device__ __forceinline__ float ord2f(unsigned u) {
    return __uint_as_float((u & 0x80000000u) ? (u ^ 0x80000000u) : ~u);
}

// Exact warp argmax (first index) over 128 values held as float4/lane.
// Returns token; *Mu_out = order-preserving uint of the max value.
__device__ __forceinline__ int warp_argmax128(float4 v, int lane, unsigned* Mu_out) {
    float m = v.x; int mi = 0;
    if (v.y > m) { m = v.y; mi = 1; }
    if (v.z > m) { m = v.z; mi = 2; }
    if (v.w > m) { m = v.w; mi = 3; }
    mi += lane * 4;
    unsigned mu = f2ord(m);
    unsigned Mu = __reduce_max_sync(0xFFFFFFFFu, mu);
    unsigned cand = (mu == Mu) ? (unsigned)mi : 0xFFFFFFFFu;
    *Mu_out = Mu;
    return (int)__reduce_min_sync(0xFFFFFFFFu, cand);
}

// ---------------------------------------------------------------------------
// Fused kernel (V=128, T%64==0): block = 256 threads = 8 warps = 64 rows.
// Exact two-REDUX argmax per row; exp-sum WITHOUT max subtraction (chain-
// independent of the reduction; exact max recovered from Mu). keep computed
// block-locally via smem tokens; boundary prev recomputed (1 row / 64).
// score = sum over t<len of (M - log sum exp(x)), atomicAdd per warp-group.
// ---------------------------------------------------------------------------
__global__ void __launch_bounds__(256) ctc_fused_v128(
    const float* __restrict__ feat, const int* __restrict__ lengths,
    float* __restrict__ tok_out, float* __restrict__ keep_out,
    float* __restrict__ score_out, int T)
{
    __shared__ int s_tok[65];                 // [0] = prev token entering block
    const int tid  = threadIdx.x;
    const int lane = tid & 31;
    const int w    = tid >> 5;
    const int R    = blockIdx.x * 64;         // first row of block
    const int b    = R / T;                   // T%64==0 -> whole block in batch b
    const int tb   = R - b * T;               // frame index of block start
    const int len  = lengths[b];
    const float4* f4 = reinterpret_cast<const float4*>(feat);
    const int row0 = R + w * 8;
    const int t0   = tb + w * 8;

    // Boundary token (row R-1), warp 0 only. BLANK at batch start.
    if (w == 0) {
        int bt = 0;
        if (tb != 0) {
            unsigned Mu;
            bt = warp_argmax128(f4[(size_t)(R - 1) * 32 + lane], lane, &Mu);
        }
        if (lane == 0) s_tok[0] = bt;
    }

    // Front-batched loads: 8 rows per warp.
    float4 v[8];
    #pragma unroll
    for (int r = 0; r < 8; r++)
        v[r] = f4[(size_t)(row0 + r) * 32 + lane];

    const int nvalid = len - t0;              // rows [0,nvalid) of group valid
    float acc = 0.f;
    #pragma unroll
    for (int r = 0; r < 8; r++) {
        unsigned Mu;
        int token = warp_argmax128(v[r], lane, &Mu);
        if (lane == 0) s_tok[1 + w * 8 + r] = token;

        if (r < nvalid) {                     // warp-uniform
            // sum exp(x) -- independent of the reduction above
            float s = __expf(v[r].x) + __expf(v[r].y) +
                      __expf(v[r].z) + __expf(v[r].w);
            #pragma unroll
            for (int o = 16; o; o >>= 1)
                s += __shfl_xor_sync(0xFFFFFFFFu, s, o);
            acc += ord2f(Mu) - __logf(s);     // max(log_softmax) = M - lse
        }
    }
    if (lane == 0 && nvalid > 0) atomicAdd(score_out + b, acc);

    __syncthreads();

    // tok + keep for the block's 64 rows.
    if (tid < 64) {
        int cur  = s_tok[1 + tid];
        int prev = s_tok[tid];
        int t = tb + tid;
        tok_out[R + tid]  = (float)cur;
        keep_out[R + tid] = (cur != 0 && cur != prev && t < len) ? 1.f : 0.f;
    }
}

// ---------------------------------------------------------------------------
// Generic fallbacks (any V / T). Not expected to run for this shape.
// ---------------------------------------------------------------------------
__global__ void ctc_pass1_gen(const float* __restrict__ feat,
                              float* __restrict__ tok_out,
                              int rows, int V) {
    int warp = (blockIdx.x * blockDim.x + threadIdx.x) >> 5;
    int lane = threadIdx.x & 31;
    if (warp >= rows) return;
    const float* row = feat + (size_t)warp * V;

    float m = -INFINITY; int mi = 0;
    for (int i = lane; i < V; i += 32) {
        float x = row[i];
        if (x > m) { m = x; mi = i; }
    }
    #pragma unroll
    for (int o = 16; o; o >>= 1) {
        float om = __shfl_xor_sync(0xFFFFFFFFu, m, o);
        int   oi = __shfl_xor_sync(0xFFFFFFFFu, mi, o);
        if (om > m || (om == m && oi < mi)) { m = om; mi = oi; }
    }
    float s = 0.f;
    for (int i = lane; i < V; i += 32) s += __expf(row[i] - m);
    #pragma unroll
    for (int o = 16; o; o >>= 1) s += __shfl_xor_sync(0xFFFFFFFFu, s, o);
    if (lane == 0) { tok_out[warp] = (float)mi; g_maxscore[warp] = -__logf(s); }
}

__global__ void ctc_pass2_gen(const float* __restrict__ tok,
                              const int* __restrict__ lengths,
                              float* __restrict__ keep_out,
                              float* __restrict__ score_out,
                              int T) {
    int b = blockIdx.x;
    int len = lengths[b];
    const float* trow = tok + (size_t)b * T;
    float* krow = keep_out + (size_t)b * T;
    const float* srow = g_maxscore + (size_t)b * T;

    float acc = 0.f;
    for (int t = threadIdx.x; t < T; t += blockDim.x) {
        int cur  = (int)trow[t];
        int prev = (t == 0) ? 0 : (int)trow[t - 1];
        bool valid = (t < len);
        krow[t] = (cur != 0 && cur != prev && valid) ? 1.f : 0.f;
        if (valid) acc += srow[t];
    }
    #pragma unroll
    for (int o = 16; o; o >>= 1) acc += __shfl_xor_sync(0xFFFFFFFFu, acc, o);
    __shared__ float sh[32];
    int wid = threadIdx.x >> 5;
    if ((threadIdx.x & 31) == 0) sh[wid] = acc;
    __syncthreads();
    if (threadIdx.x == 0) {
        float s = 0.f;
        int nw = blockDim.x >> 5;
        for (int w = 0; w < nw; w++) s += sh[w];
        score_out[b] = s;
    }
}

extern "C" void kernel_launch(void* const* d_in, const int* in_sizes, int n_in,
                              void* d_out, int out_size) {
    const float* feat    = (const float*)d_in[0];
    const int*   lengths = (const int*)d_in[1];

    int B = in_sizes[1];
    int T = (out_size - B) / (2 * B);          // out = tokens(B*T) + keep(B*T) + scores(B)
    int V = (int)((long long)in_sizes[0] / ((long long)B * T));
    int rows = B * T;

    float* out   = (float*)d_out;
    float* tok   = out;
    float* keep  = out + (size_t)rows;
    float* score = out + 2 * (size_t)rows;

    if (V == 128 && (T % 64) == 0) {
        cudaMemsetAsync(score, 0, (size_t)B * sizeof(float), 0);
        int blocks = rows / 64;                // 4096 for this shape
        ctc_fused_v128<<<blocks, 256>>>(feat, lengths, tok, keep, score, T);
    } else {
        ctc_pass1_gen<<<(rows + 7) / 8, 256>>>(feat, tok, rows, V);
        ctc_pass2_gen<<<B, 256>>>(tok, lengths, keep, score, T);
    }
}